// round 2
// baseline (speedup 1.0000x reference)
#include <cuda_runtime.h>
#include <cuda_bf16.h>

#define D 128
#define MAXN 50000
#define MAXE 600000

typedef int eidx_t;   // edge_index element type (JAX default: int64 request -> int32)

// ---------------- scratch (device globals: no allocation allowed) ----------------
__device__ float g_h[MAXN * D];      // projected features  h = x @ W
__device__ float g_s[MAXN];          // h . a_src
__device__ float g_t[MAXN];          // h . a_dst
__device__ int   g_cnt[MAXN];        // degree counts / scatter cursors
__device__ int   g_off[MAXN + 1];    // CSR offsets (by dst)
__device__ int   g_csr[MAXE];        // src indices grouped by dst

// ---------------- SGEMM: H[N,128] = X[N,128] @ W[128,128] ----------------
// BM=64, BN=128, BK=16, 256 threads, each thread 8x4 outputs.
__global__ void gemm128_kernel(const float* __restrict__ X,
                               const float* __restrict__ W,
                               float* __restrict__ H, int n) {
    __shared__ float xs[16][64];
    __shared__ float ws[16][128];
    const int block_row = blockIdx.x * 64;
    const int tid = threadIdx.x;
    const int tx = tid & 31;   // n-group: cols tx*4 .. tx*4+3
    const int ty = tid >> 5;   // m-group: rows ty*8 .. ty*8+7

    float acc[8][4];
#pragma unroll
    for (int i = 0; i < 8; i++)
#pragma unroll
        for (int j = 0; j < 4; j++) acc[i][j] = 0.0f;

    const int lrow = tid >> 2;        // 0..63
    const int lcol = (tid & 3) * 4;   // 0,4,8,12

    for (int k0 = 0; k0 < D; k0 += 16) {
        // load X tile [64][16] (transposed into xs[k][m])
        int grow = block_row + lrow;
        float4 xv = make_float4(0.f, 0.f, 0.f, 0.f);
        if (grow < n) xv = *(const float4*)&X[grow * D + k0 + lcol];
        xs[lcol + 0][lrow] = xv.x;
        xs[lcol + 1][lrow] = xv.y;
        xs[lcol + 2][lrow] = xv.z;
        xs[lcol + 3][lrow] = xv.w;
        // load W tile [16][128]: 512 float4, 2 per thread
#pragma unroll
        for (int r = 0; r < 2; r++) {
            int idx = tid + r * 256;          // 0..511
            int wk = idx >> 5;                // row in tile (0..15)
            int wn = (idx & 31) * 4;          // col (0..124)
            *(float4*)&ws[wk][wn] = *(const float4*)&W[(k0 + wk) * D + wn];
        }
        __syncthreads();
#pragma unroll
        for (int k = 0; k < 16; k++) {
            float a[8];
#pragma unroll
            for (int i = 0; i < 8; i++) a[i] = xs[k][ty * 8 + i];
            float4 b = *(float4*)&ws[k][tx * 4];
#pragma unroll
            for (int i = 0; i < 8; i++) {
                acc[i][0] += a[i] * b.x;
                acc[i][1] += a[i] * b.y;
                acc[i][2] += a[i] * b.z;
                acc[i][3] += a[i] * b.w;
            }
        }
        __syncthreads();
    }
#pragma unroll
    for (int i = 0; i < 8; i++) {
        int grow = block_row + ty * 8 + i;
        if (grow < n)
            *(float4*)&H[grow * D + tx * 4] =
                make_float4(acc[i][0], acc[i][1], acc[i][2], acc[i][3]);
    }
}

// ---------------- per-node attention dots: s = h.a_src, t = h.a_dst ----------------
__global__ void st_kernel(const float* __restrict__ h,
                          const float* __restrict__ a_src,
                          const float* __restrict__ a_dst,
                          float* __restrict__ s, float* __restrict__ t, int n) {
    int warp = (blockIdx.x * blockDim.x + threadIdx.x) >> 5;
    int lane = threadIdx.x & 31;
    if (warp >= n) return;
    float4 hv = *(const float4*)&h[warp * D + lane * 4];
    float4 as = *(const float4*)&a_src[lane * 4];
    float4 ad = *(const float4*)&a_dst[lane * 4];
    float ss = hv.x * as.x + hv.y * as.y + hv.z * as.z + hv.w * as.w;
    float tt = hv.x * ad.x + hv.y * ad.y + hv.z * ad.z + hv.w * ad.w;
#pragma unroll
    for (int o = 16; o > 0; o >>= 1) {
        ss += __shfl_xor_sync(0xffffffffu, ss, o);
        tt += __shfl_xor_sync(0xffffffffu, tt, o);
    }
    if (lane == 0) { s[warp] = ss; t[warp] = tt; }
}

// ---------------- dst-degree histogram ----------------
__global__ void hist_kernel(const eidx_t* __restrict__ ei, int* __restrict__ cnt,
                            int E, int N) {
    int i = blockIdx.x * blockDim.x + threadIdx.x;
    if (i < E) {
        int dst = (int)ei[E + i];
        if ((unsigned)dst < (unsigned)N) atomicAdd(&cnt[dst], 1);
    }
}

// ---------------- single-block exclusive scan of counts ----------------
__global__ void scan_kernel(const int* __restrict__ cnt, int* __restrict__ off, int n) {
    __shared__ int sm[1024];
    __shared__ int s_carry;
    const int tid = threadIdx.x;
    if (tid == 0) s_carry = 0;
    __syncthreads();
    for (int base = 0; base < n; base += 1024) {
        int v = (base + tid < n) ? cnt[base + tid] : 0;
        sm[tid] = v;
        __syncthreads();
#pragma unroll
        for (int s = 1; s < 1024; s <<= 1) {
            int y = (tid >= s) ? sm[tid - s] : 0;
            __syncthreads();
            sm[tid] += y;
            __syncthreads();
        }
        int carry = s_carry;
        if (base + tid < n) off[base + tid] = carry + sm[tid] - v;
        __syncthreads();
        if (tid == 1023) s_carry = carry + sm[1023];
        __syncthreads();
    }
    if (tid == 0) off[n] = s_carry;
}

// ---------------- scatter src ids into CSR (grouped by dst) ----------------
__global__ void scatter_kernel(const eidx_t* __restrict__ ei,
                               const int* __restrict__ off, int* __restrict__ cur,
                               int* __restrict__ csr, int E, int N) {
    int i = blockIdx.x * blockDim.x + threadIdx.x;
    if (i < E) {
        int src = (int)ei[i];
        int dst = (int)ei[E + i];
        if ((unsigned)src >= (unsigned)N || (unsigned)dst >= (unsigned)N) return;
        int pos = off[dst] + atomicAdd(&cur[dst], 1);
        if (pos < MAXE) csr[pos] = src;
    }
}

// ---------------- warp-per-node online-softmax aggregation ----------------
__global__ void aggregate_kernel(const float* __restrict__ h,
                                 const float* __restrict__ s,
                                 const float* __restrict__ t,
                                 const int* __restrict__ off,
                                 const int* __restrict__ csr,
                                 const float* __restrict__ bias,
                                 float* __restrict__ out, int n) {
    int node = (blockIdx.x * blockDim.x + threadIdx.x) >> 5;
    int lane = threadIdx.x & 31;
    if (node >= n) return;

    float tn = __ldg(&t[node]);
    // self-loop edge first (always present): src = node
    float e0 = __ldg(&s[node]) + tn;
    e0 = (e0 > 0.f) ? e0 : 0.2f * e0;
    float m = e0;
    float denom = 1.0f;                       // exp(e0 - m) = 1
    float4 acc = *(const float4*)&h[node * D + lane * 4];

    int beg = off[node], end = off[node + 1];
    for (int i = beg; i < end; i++) {
        int src = __ldg(&csr[i]);
        float e = __ldg(&s[src]) + tn;
        e = (e > 0.f) ? e : 0.2f * e;
        float w;
        if (e > m) {
            float r = __expf(m - e);
            denom = denom * r + 1.0f;
            acc.x *= r; acc.y *= r; acc.z *= r; acc.w *= r;
            m = e;
            w = 1.0f;
        } else {
            w = __expf(e - m);
            denom += w;
        }
        float4 hv = *(const float4*)&h[src * D + lane * 4];
        acc.x += w * hv.x;
        acc.y += w * hv.y;
        acc.z += w * hv.z;
        acc.w += w * hv.w;
    }
    float inv = 1.0f / (denom + 1e-16f);
    float4 bv = *(const float4*)&bias[lane * 4];
    float4 o;
    o.x = fmaxf(acc.x * inv + bv.x, 0.f);
    o.y = fmaxf(acc.y * inv + bv.y, 0.f);
    o.z = fmaxf(acc.z * inv + bv.z, 0.f);
    o.w = fmaxf(acc.w * inv + bv.w, 0.f);
    *(float4*)&out[node * D + lane * 4] = o;
}

// ---------------- host orchestration ----------------
static void run_graph(const float* x, const eidx_t* ei, const float* W,
                      const float* a_src, const float* a_dst, const float* bias,
                      float* out, int N, int E,
                      float* h, float* s, float* t, int* cnt, int* off, int* csr) {
    gemm128_kernel<<<(N + 63) / 64, 256>>>(x, W, h, N);
    st_kernel<<<(N * 32 + 255) / 256, 256>>>(h, a_src, a_dst, s, t, N);
    cudaMemsetAsync(cnt, 0, N * sizeof(int));
    hist_kernel<<<(E + 255) / 256, 256>>>(ei, cnt, E, N);
    scan_kernel<<<1, 1024>>>(cnt, off, N);
    cudaMemsetAsync(cnt, 0, N * sizeof(int));
    scatter_kernel<<<(E + 255) / 256, 256>>>(ei, off, cnt, csr, E, N);
    aggregate_kernel<<<(N * 32 + 255) / 256, 256>>>(h, s, t, off, csr, bias, out, N);
}

extern "C" void kernel_launch(void* const* d_in, const int* in_sizes, int n_in,
                              void* d_out, int out_size) {
    const float*   x1  = (const float*)d_in[0];
    const eidx_t*  ei1 = (const eidx_t*)d_in[1];
    const float*   x2  = (const float*)d_in[3];
    const eidx_t*  ei2 = (const eidx_t*)d_in[4];
    const float*   W1  = (const float*)d_in[6];
    const float*   as1 = (const float*)d_in[7];
    const float*   ad1 = (const float*)d_in[8];
    const float*   b1  = (const float*)d_in[9];
    const float*   W2  = (const float*)d_in[10];
    const float*   as2 = (const float*)d_in[11];
    const float*   ad2 = (const float*)d_in[12];
    const float*   b2  = (const float*)d_in[13];

    int N = in_sizes[0] / D;
    int E = in_sizes[1] / 2;
    if (N > MAXN) N = MAXN;
    if (E > MAXE) E = MAXE;

    float* out = (float*)d_out;

    float *h, *s, *t;
    int *cnt, *off, *csr;
    cudaGetSymbolAddress((void**)&h,   g_h);
    cudaGetSymbolAddress((void**)&s,   g_s);
    cudaGetSymbolAddress((void**)&t,   g_t);
    cudaGetSymbolAddress((void**)&cnt, g_cnt);
    cudaGetSymbolAddress((void**)&off, g_off);
    cudaGetSymbolAddress((void**)&csr, g_csr);

    run_graph(x1, ei1, W1, as1, ad1, b1, out,          N, E, h, s, t, cnt, off, csr);
    run_graph(x2, ei2, W2, as2, ad2, b2, out + N * D,  N, E, h, s, t, cnt, off, csr);
}

// round 3
// speedup vs baseline: 1.6411x; 1.6411x over previous
#include <cuda_runtime.h>
#include <cuda_bf16.h>

#define D 128
#define MAXN 50000
#define MAXE 600000

typedef int eidx_t;   // edge_index is int32 (JAX default x64-disabled)

// ---------------- scratch (device globals) ----------------
__device__ float g_h[MAXN * D];      // projected features  h = x @ W
__device__ float g_s[MAXN];          // h . a_src
__device__ float g_t[MAXN];          // h . a_dst
__device__ int   g_cnt[MAXN];        // degree counts / scatter cursors
__device__ int   g_off[MAXN + 1];    // CSR offsets (by dst)
__device__ int   g_csr[MAXE];        // src indices grouped by dst
__device__ int   g_bsum[64];         // per-block scan partials

// ---------------- SGEMM + fused attention dots ----------------
// H[N,128] = X[N,128] @ W[128,128]; also s = H.a_src, t = H.a_dst per row.
// BM=64, BN=128, BK=16, 256 threads, each thread 8x4 outputs.
__global__ void gemm128_kernel(const float* __restrict__ X,
                               const float* __restrict__ W,
                               const float* __restrict__ a_src,
                               const float* __restrict__ a_dst,
                               float* __restrict__ H,
                               float* __restrict__ s,
                               float* __restrict__ t, int n) {
    __shared__ float xs[16][64];
    __shared__ float ws[16][128];
    const int block_row = blockIdx.x * 64;
    const int tid = threadIdx.x;
    const int tx = tid & 31;   // n-group: cols tx*4 .. tx*4+3
    const int ty = tid >> 5;   // m-group: rows ty*8 .. ty*8+7

    float acc[8][4];
#pragma unroll
    for (int i = 0; i < 8; i++)
#pragma unroll
        for (int j = 0; j < 4; j++) acc[i][j] = 0.0f;

    const int lrow = tid >> 2;        // 0..63
    const int lcol = (tid & 3) * 4;   // 0,4,8,12

    for (int k0 = 0; k0 < D; k0 += 16) {
        int grow = block_row + lrow;
        float4 xv = make_float4(0.f, 0.f, 0.f, 0.f);
        if (grow < n) xv = *(const float4*)&X[grow * D + k0 + lcol];
        xs[lcol + 0][lrow] = xv.x;
        xs[lcol + 1][lrow] = xv.y;
        xs[lcol + 2][lrow] = xv.z;
        xs[lcol + 3][lrow] = xv.w;
#pragma unroll
        for (int r = 0; r < 2; r++) {
            int idx = tid + r * 256;
            int wk = idx >> 5;
            int wn = (idx & 31) * 4;
            *(float4*)&ws[wk][wn] = *(const float4*)&W[(k0 + wk) * D + wn];
        }
        __syncthreads();
#pragma unroll
        for (int k = 0; k < 16; k++) {
            float a[8];
#pragma unroll
            for (int i = 0; i < 8; i++) a[i] = xs[k][ty * 8 + i];
            float4 b = *(float4*)&ws[k][tx * 4];
#pragma unroll
            for (int i = 0; i < 8; i++) {
                acc[i][0] += a[i] * b.x;
                acc[i][1] += a[i] * b.y;
                acc[i][2] += a[i] * b.z;
                acc[i][3] += a[i] * b.w;
            }
        }
        __syncthreads();
    }

    // store H + fused per-row dots with a_src/a_dst (warp owns full 128-wide rows)
    float4 as = *(const float4*)&a_src[tx * 4];
    float4 ad = *(const float4*)&a_dst[tx * 4];
#pragma unroll
    for (int i = 0; i < 8; i++) {
        int grow = block_row + ty * 8 + i;
        float ps = acc[i][0] * as.x + acc[i][1] * as.y + acc[i][2] * as.z + acc[i][3] * as.w;
        float pt = acc[i][0] * ad.x + acc[i][1] * ad.y + acc[i][2] * ad.z + acc[i][3] * ad.w;
#pragma unroll
        for (int o = 16; o > 0; o >>= 1) {
            ps += __shfl_xor_sync(0xffffffffu, ps, o);
            pt += __shfl_xor_sync(0xffffffffu, pt, o);
        }
        if (grow < n) {
            *(float4*)&H[grow * D + tx * 4] =
                make_float4(acc[i][0], acc[i][1], acc[i][2], acc[i][3]);
            if (tx == 0) { s[grow] = ps; t[grow] = pt; }
        }
    }
}

// ---------------- dst-degree histogram ----------------
__global__ void hist_kernel(const eidx_t* __restrict__ ei, int* __restrict__ cnt,
                            int E, int N) {
    int i = blockIdx.x * blockDim.x + threadIdx.x;
    if (i < E) {
        int dst = (int)ei[E + i];
        if ((unsigned)dst < (unsigned)N) atomicAdd(&cnt[dst], 1);
    }
}

// ---------------- multi-block scan: K1 per-block inclusive scan ----------------
__global__ void scan1_kernel(const int* __restrict__ cnt, int* __restrict__ incl,
                             int n) {
    __shared__ int warp_sums[32];
    int i = blockIdx.x * 1024 + threadIdx.x;
    int lane = threadIdx.x & 31, wid = threadIdx.x >> 5;
    int v = (i < n) ? cnt[i] : 0;
    int x = v;
#pragma unroll
    for (int o = 1; o < 32; o <<= 1) {
        int y = __shfl_up_sync(0xffffffffu, x, o);
        if (lane >= o) x += y;
    }
    if (lane == 31) warp_sums[wid] = x;
    __syncthreads();
    if (wid == 0) {
        int sx = warp_sums[lane];
#pragma unroll
        for (int o = 1; o < 32; o <<= 1) {
            int y = __shfl_up_sync(0xffffffffu, sx, o);
            if (lane >= o) sx += y;
        }
        warp_sums[lane] = sx;
    }
    __syncthreads();
    if (wid > 0) x += warp_sums[wid - 1];
    if (i < n) incl[i] = x;
    if (threadIdx.x == 1023) g_bsum[blockIdx.x] = x;
}

// ---------------- K2: exclusive scan of <=64 block sums ----------------
__global__ void scan2_kernel(int nblocks) {
    __shared__ int sm[64];
    int tid = threadIdx.x;
    int v = (tid < nblocks) ? g_bsum[tid] : 0;
    sm[tid] = v;
    __syncthreads();
#pragma unroll
    for (int o = 1; o < 64; o <<= 1) {
        int y = (tid >= o) ? sm[tid - o] : 0;
        __syncthreads();
        sm[tid] += y;
        __syncthreads();
    }
    g_bsum[tid] = sm[tid] - v;   // exclusive
}

// ---------------- K3: add carry, convert inclusive->exclusive offsets ----------------
__global__ void scan3_kernel(const int* __restrict__ cnt, int* __restrict__ off,
                             int n) {
    int i = blockIdx.x * 1024 + threadIdx.x;
    if (i < n) {
        int carry = g_bsum[blockIdx.x];
        int incl = off[i];
        off[i] = incl - cnt[i] + carry;
        if (i == n - 1) off[n] = incl + carry;
    }
}

// ---------------- scatter src ids into CSR (grouped by dst) ----------------
__global__ void scatter_kernel(const eidx_t* __restrict__ ei,
                               const int* __restrict__ off, int* __restrict__ cur,
                               int* __restrict__ csr, int E, int N) {
    int i = blockIdx.x * blockDim.x + threadIdx.x;
    if (i < E) {
        int src = (int)ei[i];
        int dst = (int)ei[E + i];
        if ((unsigned)src >= (unsigned)N || (unsigned)dst >= (unsigned)N) return;
        int pos = off[dst] + atomicAdd(&cur[dst], 1);
        if (pos < MAXE) csr[pos] = src;
    }
}

// ---------------- warp-per-node online-softmax aggregation ----------------
__global__ void aggregate_kernel(const float* __restrict__ h,
                                 const float* __restrict__ s,
                                 const float* __restrict__ t,
                                 const int* __restrict__ off,
                                 const int* __restrict__ csr,
                                 const float* __restrict__ bias,
                                 float* __restrict__ out, int n) {
    int node = (blockIdx.x * blockDim.x + threadIdx.x) >> 5;
    int lane = threadIdx.x & 31;
    if (node >= n) return;

    float tn = __ldg(&t[node]);
    float e0 = __ldg(&s[node]) + tn;        // self-loop
    e0 = (e0 > 0.f) ? e0 : 0.2f * e0;
    float m = e0;
    float denom = 1.0f;
    float4 acc = *(const float4*)&h[node * D + lane * 4];

    int beg = off[node], end = off[node + 1];
    for (int i = beg; i < end; i++) {
        int src = __ldg(&csr[i]);
        float e = __ldg(&s[src]) + tn;
        e = (e > 0.f) ? e : 0.2f * e;
        float w;
        if (e > m) {
            float r = __expf(m - e);
            denom = denom * r + 1.0f;
            acc.x *= r; acc.y *= r; acc.z *= r; acc.w *= r;
            m = e;
            w = 1.0f;
        } else {
            w = __expf(e - m);
            denom += w;
        }
        float4 hv = *(const float4*)&h[src * D + lane * 4];
        acc.x += w * hv.x;
        acc.y += w * hv.y;
        acc.z += w * hv.z;
        acc.w += w * hv.w;
    }
    float inv = 1.0f / (denom + 1e-16f);
    float4 bv = *(const float4*)&bias[lane * 4];
    float4 o;
    o.x = fmaxf(acc.x * inv + bv.x, 0.f);
    o.y = fmaxf(acc.y * inv + bv.y, 0.f);
    o.z = fmaxf(acc.z * inv + bv.z, 0.f);
    o.w = fmaxf(acc.w * inv + bv.w, 0.f);
    *(float4*)&out[node * D + lane * 4] = o;
}

// ---------------- host orchestration ----------------
static void run_graph(const float* x, const eidx_t* ei, const float* W,
                      const float* a_src, const float* a_dst, const float* bias,
                      float* out, int N, int E,
                      float* h, float* s, float* t, int* cnt, int* off, int* csr) {
    int nblk = (N + 1023) / 1024;
    gemm128_kernel<<<(N + 63) / 64, 256>>>(x, W, a_src, a_dst, h, s, t, N);
    cudaMemsetAsync(cnt, 0, N * sizeof(int));
    hist_kernel<<<(E + 255) / 256, 256>>>(ei, cnt, E, N);
    scan1_kernel<<<nblk, 1024>>>(cnt, off, N);
    scan2_kernel<<<1, 64>>>(nblk);
    scan3_kernel<<<nblk, 1024>>>(cnt, off, N);
    cudaMemsetAsync(cnt, 0, N * sizeof(int));
    scatter_kernel<<<(E + 255) / 256, 256>>>(ei, off, cnt, csr, E, N);
    aggregate_kernel<<<(N * 32 + 255) / 256, 256>>>(h, s, t, off, csr, bias, out, N);
}

extern "C" void kernel_launch(void* const* d_in, const int* in_sizes, int n_in,
                              void* d_out, int out_size) {
    const float*   x1  = (const float*)d_in[0];
    const eidx_t*  ei1 = (const eidx_t*)d_in[1];
    const float*   x2  = (const float*)d_in[3];
    const eidx_t*  ei2 = (const eidx_t*)d_in[4];
    const float*   W1  = (const float*)d_in[6];
    const float*   as1 = (const float*)d_in[7];
    const float*   ad1 = (const float*)d_in[8];
    const float*   b1  = (const float*)d_in[9];
    const float*   W2  = (const float*)d_in[10];
    const float*   as2 = (const float*)d_in[11];
    const float*   ad2 = (const float*)d_in[12];
    const float*   b2  = (const float*)d_in[13];

    int N = in_sizes[0] / D;
    int E = in_sizes[1] / 2;
    if (N > MAXN) N = MAXN;
    if (E > MAXE) E = MAXE;

    float* out = (float*)d_out;

    float *h, *s, *t;
    int *cnt, *off, *csr;
    cudaGetSymbolAddress((void**)&h,   g_h);
    cudaGetSymbolAddress((void**)&s,   g_s);
    cudaGetSymbolAddress((void**)&t,   g_t);
    cudaGetSymbolAddress((void**)&cnt, g_cnt);
    cudaGetSymbolAddress((void**)&off, g_off);
    cudaGetSymbolAddress((void**)&csr, g_csr);

    run_graph(x1, ei1, W1, as1, ad1, b1, out,          N, E, h, s, t, cnt, off, csr);
    run_graph(x2, ei2, W2, as2, ad2, b2, out + N * D,  N, E, h, s, t, cnt, off, csr);
}

// round 4
// speedup vs baseline: 1.6869x; 1.0279x over previous
#include <cuda_runtime.h>
#include <cuda_bf16.h>

#define D 128
#define MAXN 50000
#define MAXE 600000
#define NEGINF (-1e30f)

typedef int eidx_t;   // edge_index is int32 (JAX default x64-disabled)

// ---------------- scratch (device globals) ----------------
__device__ float g_h[2 * MAXN * D];    // projected features, both graphs
__device__ float g_s[2 * MAXN];        // h . a_src
__device__ float g_t[2 * MAXN];        // h . a_dst
__device__ int   g_cnt[2 * MAXN];      // degree counts / scatter cursors
__device__ int   g_off[2 * MAXN + 1];  // CSR offsets (by global dst)
__device__ int   g_csr[2 * MAXE];      // global src ids grouped by dst
__device__ int   g_bsum[128];          // per-block scan partials

// ---------------- SGEMM + fused attention dots (both graphs) ----------------
// 128x128 block tile, BK=8, 256 threads, 8x8 outputs per thread.
// blockIdx.y selects graph (inputs/weights); H/s/t indexed by global row.
__global__ void gemm128_kernel(const float* __restrict__ x1,
                               const float* __restrict__ x2,
                               const float* __restrict__ W1,
                               const float* __restrict__ W2,
                               const float* __restrict__ as1,
                               const float* __restrict__ ad1,
                               const float* __restrict__ as2,
                               const float* __restrict__ ad2,
                               float* __restrict__ H,
                               float* __restrict__ s,
                               float* __restrict__ t, int n) {
    __shared__ float xs[8][128];   // [k][m]
    __shared__ float ws[8][128];   // [k][n]

    const int g = blockIdx.y;
    const float* __restrict__ X = g ? x2 : x1;
    const float* __restrict__ W = g ? W2 : W1;
    const float* __restrict__ a_src = g ? as2 : as1;
    const float* __restrict__ a_dst = g ? ad2 : ad1;
    const int gbase = g * n;

    const int block_row = blockIdx.x * 128;
    const int tid = threadIdx.x;
    const int tr = tid >> 4;          // 0..15 -> rows tr*8..+7
    const int tc = tid & 15;          // 0..15 -> cols tc*8..+7

    // loader coords
    const int xrow = tid >> 1;            // 0..127
    const int xcg  = (tid & 1) * 4;       // 0 or 4
    const int wr   = tid >> 5;            // 0..7
    const int wc   = (tid & 31) * 4;      // 0..124

    float acc[8][8];
#pragma unroll
    for (int i = 0; i < 8; i++)
#pragma unroll
        for (int j = 0; j < 8; j++) acc[i][j] = 0.0f;

    for (int k0 = 0; k0 < D; k0 += 8) {
        int grow = block_row + xrow;
        float4 xv = make_float4(0.f, 0.f, 0.f, 0.f);
        if (grow < n) xv = *(const float4*)&X[grow * D + k0 + xcg];
        xs[xcg + 0][xrow] = xv.x;
        xs[xcg + 1][xrow] = xv.y;
        xs[xcg + 2][xrow] = xv.z;
        xs[xcg + 3][xrow] = xv.w;
        *(float4*)&ws[wr][wc] = *(const float4*)&W[(k0 + wr) * D + wc];
        __syncthreads();
#pragma unroll
        for (int k = 0; k < 8; k++) {
            float a[8], b[8];
            *(float4*)&a[0] = *(float4*)&xs[k][tr * 8];
            *(float4*)&a[4] = *(float4*)&xs[k][tr * 8 + 4];
            *(float4*)&b[0] = *(float4*)&ws[k][tc * 8];
            *(float4*)&b[4] = *(float4*)&ws[k][tc * 8 + 4];
#pragma unroll
            for (int i = 0; i < 8; i++)
#pragma unroll
                for (int j = 0; j < 8; j++) acc[i][j] += a[i] * b[j];
        }
        __syncthreads();
    }

    // epilogue: store H rows + fused dot-products with a_src/a_dst.
    // threads sharing tr form a contiguous 16-lane (half-warp) group.
    float asv[8], adv[8];
#pragma unroll
    for (int j = 0; j < 8; j++) {
        asv[j] = a_src[tc * 8 + j];
        adv[j] = a_dst[tc * 8 + j];
    }
#pragma unroll
    for (int i = 0; i < 8; i++) {
        int row = block_row + tr * 8 + i;
        float ps = 0.f, pt = 0.f;
#pragma unroll
        for (int j = 0; j < 8; j++) {
            ps += acc[i][j] * asv[j];
            pt += acc[i][j] * adv[j];
        }
#pragma unroll
        for (int o = 8; o > 0; o >>= 1) {
            ps += __shfl_xor_sync(0xffffffffu, ps, o);
            pt += __shfl_xor_sync(0xffffffffu, pt, o);
        }
        if (row < n) {
            float* hrow = &H[(gbase + row) * D + tc * 8];
            *(float4*)&hrow[0] = *(float4*)&acc[i][0];
            *(float4*)&hrow[4] = *(float4*)&acc[i][4];
            if (tc == 0) { s[gbase + row] = ps; t[gbase + row] = pt; }
        }
    }
}

// ---------------- dst-degree histogram (both edge lists) ----------------
__global__ void hist_kernel(const eidx_t* __restrict__ ei1,
                            const eidx_t* __restrict__ ei2,
                            int* __restrict__ cnt, int E, int N) {
    int i = blockIdx.x * blockDim.x + threadIdx.x;
    if (i < E) {
        int dst = (int)ei1[E + i];
        if ((unsigned)dst < (unsigned)N) atomicAdd(&cnt[dst], 1);
    } else if (i < 2 * E) {
        int dst = (int)ei2[E + (i - E)];
        if ((unsigned)dst < (unsigned)N) atomicAdd(&cnt[N + dst], 1);
    }
}

// ---------------- multi-block scan: K1 per-block inclusive scan ----------------
__global__ void scan1_kernel(const int* __restrict__ cnt, int* __restrict__ incl,
                             int n) {
    __shared__ int warp_sums[32];
    int i = blockIdx.x * 1024 + threadIdx.x;
    int lane = threadIdx.x & 31, wid = threadIdx.x >> 5;
    int v = (i < n) ? cnt[i] : 0;
    int x = v;
#pragma unroll
    for (int o = 1; o < 32; o <<= 1) {
        int y = __shfl_up_sync(0xffffffffu, x, o);
        if (lane >= o) x += y;
    }
    if (lane == 31) warp_sums[wid] = x;
    __syncthreads();
    if (wid == 0) {
        int sx = warp_sums[lane];
#pragma unroll
        for (int o = 1; o < 32; o <<= 1) {
            int y = __shfl_up_sync(0xffffffffu, sx, o);
            if (lane >= o) sx += y;
        }
        warp_sums[lane] = sx;
    }
    __syncthreads();
    if (wid > 0) x += warp_sums[wid - 1];
    if (i < n) incl[i] = x;
    if (threadIdx.x == 1023) g_bsum[blockIdx.x] = x;
}

// ---------------- K2: exclusive scan of <=128 block sums ----------------
__global__ void scan2_kernel(int nblocks) {
    __shared__ int sm[128];
    int tid = threadIdx.x;
    int v = (tid < nblocks) ? g_bsum[tid] : 0;
    sm[tid] = v;
    __syncthreads();
#pragma unroll
    for (int o = 1; o < 128; o <<= 1) {
        int y = (tid >= o) ? sm[tid - o] : 0;
        __syncthreads();
        sm[tid] += y;
        __syncthreads();
    }
    g_bsum[tid] = sm[tid] - v;   // exclusive
}

// ---------------- K3: add carry, inclusive->exclusive, zero cnt ----------------
__global__ void scan3_kernel(int* __restrict__ cnt, int* __restrict__ off, int n) {
    int i = blockIdx.x * 1024 + threadIdx.x;
    if (i < n) {
        int carry = g_bsum[blockIdx.x];
        int incl = off[i];
        off[i] = incl - cnt[i] + carry;
        cnt[i] = 0;                         // reset cursors for scatter
        if (i == n - 1) off[n] = incl + carry;
    }
}

// ---------------- scatter global src ids into CSR (grouped by dst) ----------------
__global__ void scatter_kernel(const eidx_t* __restrict__ ei1,
                               const eidx_t* __restrict__ ei2,
                               const int* __restrict__ off, int* __restrict__ cur,
                               int* __restrict__ csr, int E, int N) {
    int i = blockIdx.x * blockDim.x + threadIdx.x;
    int g, j;
    const eidx_t* ei;
    if (i < E)           { g = 0; j = i;     ei = ei1; }
    else if (i < 2 * E)  { g = 1; j = i - E; ei = ei2; }
    else return;
    int src = (int)ei[j];
    int dst = (int)ei[E + j];
    if ((unsigned)src >= (unsigned)N || (unsigned)dst >= (unsigned)N) return;
    int gd = g * N + dst;
    int pos = off[gd] + atomicAdd(&cur[gd], 1);
    if (pos < 2 * MAXE) csr[pos] = g * N + src;
}

// ---------------- warp-per-node chunked-softmax aggregation ----------------
__global__ void aggregate_kernel(const float* __restrict__ h,
                                 const float* __restrict__ s,
                                 const float* __restrict__ t,
                                 const int* __restrict__ off,
                                 const int* __restrict__ csr,
                                 const float* __restrict__ b1,
                                 const float* __restrict__ b2,
                                 float* __restrict__ out, int N, int n2) {
    int node = (blockIdx.x * blockDim.x + threadIdx.x) >> 5;
    int lane = threadIdx.x & 31;
    if (node >= n2) return;

    float tn = __ldg(&t[node]);
    float e0 = __ldg(&s[node]) + tn;       // self-loop
    e0 = (e0 > 0.f) ? e0 : 0.2f * e0;
    float m = e0;
    float denom = 1.0f;
    float4 acc = *(const float4*)&h[node * D + lane * 4];

    int beg = off[node], end = off[node + 1];
    for (int base = beg; base < end; base += 32) {
        int k = end - base; if (k > 32) k = 32;
        int src = 0;
        float e = NEGINF;
        if (lane < k) {
            src = __ldg(&csr[base + lane]);
            e = __ldg(&s[src]) + tn;
            e = (e > 0.f) ? e : 0.2f * e;
        }
        // chunk max
        float cmax = e;
#pragma unroll
        for (int o = 16; o > 0; o >>= 1)
            cmax = fmaxf(cmax, __shfl_xor_sync(0xffffffffu, cmax, o));
        float mn = fmaxf(m, cmax);
        float scale = __expf(m - mn);
        denom *= scale;
        acc.x *= scale; acc.y *= scale; acc.z *= scale; acc.w *= scale;
        m = mn;
        // parallel exp across lanes
        float w = (lane < k) ? __expf(e - m) : 0.f;
        float wsum = w;
#pragma unroll
        for (int o = 16; o > 0; o >>= 1)
            wsum += __shfl_xor_sync(0xffffffffu, wsum, o);
        denom += wsum;
        // broadcast-accumulate neighbor rows
        for (int j = 0; j < k; j++) {
            int sj = __shfl_sync(0xffffffffu, src, j);
            float wj = __shfl_sync(0xffffffffu, w, j);
            float4 hv = *(const float4*)&h[sj * D + lane * 4];
            acc.x += wj * hv.x;
            acc.y += wj * hv.y;
            acc.z += wj * hv.z;
            acc.w += wj * hv.w;
        }
    }
    float inv = 1.0f / (denom + 1e-16f);
    const float* bias = (node < N) ? b1 : b2;
    float4 bv = *(const float4*)&bias[lane * 4];
    float4 o;
    o.x = fmaxf(acc.x * inv + bv.x, 0.f);
    o.y = fmaxf(acc.y * inv + bv.y, 0.f);
    o.z = fmaxf(acc.z * inv + bv.z, 0.f);
    o.w = fmaxf(acc.w * inv + bv.w, 0.f);
    *(float4*)&out[node * D + lane * 4] = o;
}

extern "C" void kernel_launch(void* const* d_in, const int* in_sizes, int n_in,
                              void* d_out, int out_size) {
    const float*   x1  = (const float*)d_in[0];
    const eidx_t*  ei1 = (const eidx_t*)d_in[1];
    const float*   x2  = (const float*)d_in[3];
    const eidx_t*  ei2 = (const eidx_t*)d_in[4];
    const float*   W1  = (const float*)d_in[6];
    const float*   as1 = (const float*)d_in[7];
    const float*   ad1 = (const float*)d_in[8];
    const float*   b1  = (const float*)d_in[9];
    const float*   W2  = (const float*)d_in[10];
    const float*   as2 = (const float*)d_in[11];
    const float*   ad2 = (const float*)d_in[12];
    const float*   b2  = (const float*)d_in[13];

    int N = in_sizes[0] / D;
    int E = in_sizes[1] / 2;
    if (N > MAXN) N = MAXN;
    if (E > MAXE) E = MAXE;
    int n2 = 2 * N;

    float* out = (float*)d_out;

    float *h, *s, *t;
    int *cnt, *off, *csr;
    cudaGetSymbolAddress((void**)&h,   g_h);
    cudaGetSymbolAddress((void**)&s,   g_s);
    cudaGetSymbolAddress((void**)&t,   g_t);
    cudaGetSymbolAddress((void**)&cnt, g_cnt);
    cudaGetSymbolAddress((void**)&off, g_off);
    cudaGetSymbolAddress((void**)&csr, g_csr);

    int nblk = (n2 + 1023) / 1024;

    dim3 ggrid((N + 127) / 128, 2);
    gemm128_kernel<<<ggrid, 256>>>(x1, x2, W1, W2, as1, ad1, as2, ad2, h, s, t, N);
    cudaMemsetAsync(cnt, 0, n2 * sizeof(int));
    hist_kernel<<<(2 * E + 255) / 256, 256>>>(ei1, ei2, cnt, E, N);
    scan1_kernel<<<nblk, 1024>>>(cnt, off, n2);
    scan2_kernel<<<1, 128>>>(nblk);
    scan3_kernel<<<nblk, 1024>>>(cnt, off, n2);
    scatter_kernel<<<(2 * E + 255) / 256, 256>>>(ei1, ei2, off, cnt, csr, E, N);
    aggregate_kernel<<<(n2 * 32 + 255) / 256, 256>>>(h, s, t, off, csr, b1, b2,
                                                     out, N, n2);
}